// round 1
// baseline (speedup 1.0000x reference)
#include <cuda_runtime.h>
#include <math.h>

// Problem dims (fixed by the reference)
#define BDIM 8
#define RDIM 8
#define NDIM 1024
#define FDIM 256

// 64 MB scratch for e = G @ Bs  (device global array: allowed, no runtime alloc)
__device__ float g_e[(size_t)BDIM * RDIM * NDIM * FDIM];

// ---------------------------------------------------------------------------
// Kernel 1: e[b,r] (1024x256) = G[b,r] (1024x256) @ Bs[r] (256x256)   [NN]
// 128x128 tile, K-chunk 8, 256 threads, 8x8 microtile per thread.
// ---------------------------------------------------------------------------
__global__ __launch_bounds__(256)
void bilinear_gemm1(const float* __restrict__ inp, const float* __restrict__ Bw) {
    const int tile_g = blockIdx.x;          // 0..1   (cols of e: F/128)
    const int tile_n = blockIdx.y;          // 0..7   (rows:      N/128)
    const int br     = blockIdx.z;          // 0..63
    const int r      = br % RDIM;

    const float* A = inp + (size_t)br * NDIM * FDIM;     // [1024][256]
    const float* B = Bw  + (size_t)r  * FDIM * FDIM;     // [256][256]
    float*       C = g_e + (size_t)br * NDIM * FDIM;

    __shared__ float As[8][132];   // k-major, padded (132*4B = 528B, 16B aligned)
    __shared__ float Bs[8][132];

    const int tid = threadIdx.x;
    const int tx  = tid & 15;      // 0..15 -> cols
    const int ty  = tid >> 4;      // 0..15 -> rows

    // A load mapping: 128 rows x 8 k -> thread loads float4 along k, scatter-transpose
    const int arow = tid >> 1;            // 0..127
    const int akc  = (tid & 1) * 4;       // 0 or 4
    // B load mapping: 8 k-rows x 128 cols contiguous
    const int bkr  = tid >> 5;            // 0..7
    const int bcol = (tid & 31) * 4;      // 0..124

    const float* Aptr = A + (size_t)(tile_n * 128 + arow) * FDIM + akc;
    const float* Bptr = B + (size_t)bkr * FDIM + tile_g * 128 + bcol;

    float acc[8][8];
    #pragma unroll
    for (int i = 0; i < 8; i++)
        #pragma unroll
        for (int j = 0; j < 8; j++) acc[i][j] = 0.f;

    for (int k0 = 0; k0 < FDIM; k0 += 8) {
        float4 av = *(const float4*)(Aptr + k0);
        float4 bv = *(const float4*)(Bptr + (size_t)k0 * FDIM);
        As[akc + 0][arow] = av.x;
        As[akc + 1][arow] = av.y;
        As[akc + 2][arow] = av.z;
        As[akc + 3][arow] = av.w;
        *(float4*)&Bs[bkr][bcol] = bv;
        __syncthreads();

        #pragma unroll
        for (int k = 0; k < 8; k++) {
            float a[8], b[8];
            *(float4*)&a[0] = *(const float4*)&As[k][ty * 8];
            *(float4*)&a[4] = *(const float4*)&As[k][ty * 8 + 4];
            *(float4*)&b[0] = *(const float4*)&Bs[k][tx * 8];
            *(float4*)&b[4] = *(const float4*)&Bs[k][tx * 8 + 4];
            #pragma unroll
            for (int i = 0; i < 8; i++)
                #pragma unroll
                for (int j = 0; j < 8; j++)
                    acc[i][j] = fmaf(a[i], b[j], acc[i][j]);
        }
        __syncthreads();
    }

    float* Cp = C + (size_t)(tile_n * 128 + ty * 8) * FDIM + tile_g * 128 + tx * 8;
    #pragma unroll
    for (int i = 0; i < 8; i++) {
        *(float4*)(Cp + (size_t)i * FDIM)     = *(float4*)&acc[i][0];
        *(float4*)(Cp + (size_t)i * FDIM + 4) = *(float4*)&acc[i][4];
    }
}

// ---------------------------------------------------------------------------
// Kernel 2: scores[b,r] (1024x1024) = e[b,r] (1024x256) @ G[b,r]^T  [NT]
// then sigmoid. Same tiling; B tile is loaded transposed (G is [M][K] row-major).
// ---------------------------------------------------------------------------
__global__ __launch_bounds__(256)
void bilinear_gemm2(const float* __restrict__ inp, float* __restrict__ out) {
    const int tile_m = blockIdx.x;          // 0..7  (cols = other-token dim)
    const int tile_n = blockIdx.y;          // 0..7  (rows)
    const int br     = blockIdx.z;          // 0..63

    const float* A = g_e + (size_t)br * NDIM * FDIM;     // e: [1024][256]
    const float* G = inp + (size_t)br * NDIM * FDIM;     // G: [1024][256]
    float*       C = out + (size_t)br * NDIM * NDIM;

    __shared__ float As[8][132];
    __shared__ float Bs[8][132];

    const int tid = threadIdx.x;
    const int tx  = tid & 15;
    const int ty  = tid >> 4;

    const int arow = tid >> 1;
    const int akc  = (tid & 1) * 4;

    const float* Aptr = A + (size_t)(tile_n * 128 + arow) * FDIM + akc;
    const float* Gptr = G + (size_t)(tile_m * 128 + arow) * FDIM + akc;

    float acc[8][8];
    #pragma unroll
    for (int i = 0; i < 8; i++)
        #pragma unroll
        for (int j = 0; j < 8; j++) acc[i][j] = 0.f;

    for (int k0 = 0; k0 < FDIM; k0 += 8) {
        float4 av = *(const float4*)(Aptr + k0);
        float4 bv = *(const float4*)(Gptr + k0);
        As[akc + 0][arow] = av.x;
        As[akc + 1][arow] = av.y;
        As[akc + 2][arow] = av.z;
        As[akc + 3][arow] = av.w;
        Bs[akc + 0][arow] = bv.x;
        Bs[akc + 1][arow] = bv.y;
        Bs[akc + 2][arow] = bv.z;
        Bs[akc + 3][arow] = bv.w;
        __syncthreads();

        #pragma unroll
        for (int k = 0; k < 8; k++) {
            float a[8], b[8];
            *(float4*)&a[0] = *(const float4*)&As[k][ty * 8];
            *(float4*)&a[4] = *(const float4*)&As[k][ty * 8 + 4];
            *(float4*)&b[0] = *(const float4*)&Bs[k][tx * 8];
            *(float4*)&b[4] = *(const float4*)&Bs[k][tx * 8 + 4];
            #pragma unroll
            for (int i = 0; i < 8; i++)
                #pragma unroll
                for (int j = 0; j < 8; j++)
                    acc[i][j] = fmaf(a[i], b[j], acc[i][j]);
        }
        __syncthreads();
    }

    // Sigmoid epilogue + store
    float* Cp = C + (size_t)(tile_n * 128 + ty * 8) * NDIM + tile_m * 128 + tx * 8;
    #pragma unroll
    for (int i = 0; i < 8; i++) {
        float4 v0, v1;
        v0.x = 1.f / (1.f + __expf(-acc[i][0]));
        v0.y = 1.f / (1.f + __expf(-acc[i][1]));
        v0.z = 1.f / (1.f + __expf(-acc[i][2]));
        v0.w = 1.f / (1.f + __expf(-acc[i][3]));
        v1.x = 1.f / (1.f + __expf(-acc[i][4]));
        v1.y = 1.f / (1.f + __expf(-acc[i][5]));
        v1.z = 1.f / (1.f + __expf(-acc[i][6]));
        v1.w = 1.f / (1.f + __expf(-acc[i][7]));
        *(float4*)(Cp + (size_t)i * NDIM)     = v0;
        *(float4*)(Cp + (size_t)i * NDIM + 4) = v1;
    }
}

extern "C" void kernel_launch(void* const* d_in, const int* in_sizes, int n_in,
                              void* d_out, int out_size) {
    const float* inputs = (const float*)d_in[0];   // [8,8,1024,256] fp32
    const float* Bw     = (const float*)d_in[1];   // [8,256,256]    fp32
    float* out          = (float*)d_out;           // [8,8,1024,1024] fp32

    dim3 g1(FDIM / 128, NDIM / 128, BDIM * RDIM);  // (2, 8, 64)
    bilinear_gemm1<<<g1, 256>>>(inputs, Bw);

    dim3 g2(NDIM / 128, NDIM / 128, BDIM * RDIM);  // (8, 8, 64)
    bilinear_gemm2<<<g2, 256>>>(inputs, out);
}

// round 2
// speedup vs baseline: 1.0006x; 1.0006x over previous
#include <cuda_runtime.h>
#include <math.h>

// Problem dims (fixed by the reference)
#define BDIM 8
#define RDIM 8
#define NDIM 1024
#define FDIM 256

// 64 MB scratch for e = G @ Bs  (device global array: allowed, no runtime alloc)
__device__ float g_e[(size_t)BDIM * RDIM * NDIM * FDIM];

// ---------------------------------------------------------------------------
// Kernel 1: e[b,r] (1024x256) = G[b,r] (1024x256) @ Bs[r] (256x256)   [NN]
// 128x128 tile, K-chunk 8, 256 threads, 8x8 microtile per thread.
// ---------------------------------------------------------------------------
__global__ __launch_bounds__(256)
void bilinear_gemm1(const float* __restrict__ inp, const float* __restrict__ Bw) {
    const int tile_g = blockIdx.x;          // 0..1   (cols of e: F/128)
    const int tile_n = blockIdx.y;          // 0..7   (rows:      N/128)
    const int br     = blockIdx.z;          // 0..63
    const int r      = br % RDIM;

    const float* A = inp + (size_t)br * NDIM * FDIM;     // [1024][256]
    const float* B = Bw  + (size_t)r  * FDIM * FDIM;     // [256][256]
    float*       C = g_e + (size_t)br * NDIM * FDIM;

    __shared__ float As[8][132];   // k-major, padded (132*4B = 528B, 16B aligned)
    __shared__ float Bs[8][132];

    const int tid = threadIdx.x;
    const int tx  = tid & 15;      // 0..15 -> cols
    const int ty  = tid >> 4;      // 0..15 -> rows

    // A load mapping: 128 rows x 8 k -> thread loads float4 along k, scatter-transpose
    const int arow = tid >> 1;            // 0..127
    const int akc  = (tid & 1) * 4;       // 0 or 4
    // B load mapping: 8 k-rows x 128 cols contiguous
    const int bkr  = tid >> 5;            // 0..7
    const int bcol = (tid & 31) * 4;      // 0..124

    const float* Aptr = A + (size_t)(tile_n * 128 + arow) * FDIM + akc;
    const float* Bptr = B + (size_t)bkr * FDIM + tile_g * 128 + bcol;

    float acc[8][8];
    #pragma unroll
    for (int i = 0; i < 8; i++)
        #pragma unroll
        for (int j = 0; j < 8; j++) acc[i][j] = 0.f;

    for (int k0 = 0; k0 < FDIM; k0 += 8) {
        float4 av = *(const float4*)(Aptr + k0);
        float4 bv = *(const float4*)(Bptr + (size_t)k0 * FDIM);
        As[akc + 0][arow] = av.x;
        As[akc + 1][arow] = av.y;
        As[akc + 2][arow] = av.z;
        As[akc + 3][arow] = av.w;
        *(float4*)&Bs[bkr][bcol] = bv;
        __syncthreads();

        #pragma unroll
        for (int k = 0; k < 8; k++) {
            float a[8], b[8];
            *(float4*)&a[0] = *(const float4*)&As[k][ty * 8];
            *(float4*)&a[4] = *(const float4*)&As[k][ty * 8 + 4];
            *(float4*)&b[0] = *(const float4*)&Bs[k][tx * 8];
            *(float4*)&b[4] = *(const float4*)&Bs[k][tx * 8 + 4];
            #pragma unroll
            for (int i = 0; i < 8; i++)
                #pragma unroll
                for (int j = 0; j < 8; j++)
                    acc[i][j] = fmaf(a[i], b[j], acc[i][j]);
        }
        __syncthreads();
    }

    float* Cp = C + (size_t)(tile_n * 128 + ty * 8) * FDIM + tile_g * 128 + tx * 8;
    #pragma unroll
    for (int i = 0; i < 8; i++) {
        *(float4*)(Cp + (size_t)i * FDIM)     = *(float4*)&acc[i][0];
        *(float4*)(Cp + (size_t)i * FDIM + 4) = *(float4*)&acc[i][4];
    }
}

// ---------------------------------------------------------------------------
// Kernel 2: scores[b,r] (1024x1024) = e[b,r] (1024x256) @ G[b,r]^T  [NT]
// then sigmoid. Same tiling; B tile is loaded transposed (G is [M][K] row-major).
// ---------------------------------------------------------------------------
__global__ __launch_bounds__(256)
void bilinear_gemm2(const float* __restrict__ inp, float* __restrict__ out) {
    const int tile_m = blockIdx.x;          // 0..7  (cols = other-token dim)
    const int tile_n = blockIdx.y;          // 0..7  (rows)
    const int br     = blockIdx.z;          // 0..63

    const float* A = g_e + (size_t)br * NDIM * FDIM;     // e: [1024][256]
    const float* G = inp + (size_t)br * NDIM * FDIM;     // G: [1024][256]
    float*       C = out + (size_t)br * NDIM * NDIM;

    __shared__ float As[8][132];
    __shared__ float Bs[8][132];

    const int tid = threadIdx.x;
    const int tx  = tid & 15;
    const int ty  = tid >> 4;

    const int arow = tid >> 1;
    const int akc  = (tid & 1) * 4;

    const float* Aptr = A + (size_t)(tile_n * 128 + arow) * FDIM + akc;
    const float* Gptr = G + (size_t)(tile_m * 128 + arow) * FDIM + akc;

    float acc[8][8];
    #pragma unroll
    for (int i = 0; i < 8; i++)
        #pragma unroll
        for (int j = 0; j < 8; j++) acc[i][j] = 0.f;

    for (int k0 = 0; k0 < FDIM; k0 += 8) {
        float4 av = *(const float4*)(Aptr + k0);
        float4 bv = *(const float4*)(Gptr + k0);
        As[akc + 0][arow] = av.x;
        As[akc + 1][arow] = av.y;
        As[akc + 2][arow] = av.z;
        As[akc + 3][arow] = av.w;
        Bs[akc + 0][arow] = bv.x;
        Bs[akc + 1][arow] = bv.y;
        Bs[akc + 2][arow] = bv.z;
        Bs[akc + 3][arow] = bv.w;
        __syncthreads();

        #pragma unroll
        for (int k = 0; k < 8; k++) {
            float a[8], b[8];
            *(float4*)&a[0] = *(const float4*)&As[k][ty * 8];
            *(float4*)&a[4] = *(const float4*)&As[k][ty * 8 + 4];
            *(float4*)&b[0] = *(const float4*)&Bs[k][tx * 8];
            *(float4*)&b[4] = *(const float4*)&Bs[k][tx * 8 + 4];
            #pragma unroll
            for (int i = 0; i < 8; i++)
                #pragma unroll
                for (int j = 0; j < 8; j++)
                    acc[i][j] = fmaf(a[i], b[j], acc[i][j]);
        }
        __syncthreads();
    }

    // Sigmoid epilogue + store
    float* Cp = C + (size_t)(tile_n * 128 + ty * 8) * NDIM + tile_m * 128 + tx * 8;
    #pragma unroll
    for (int i = 0; i < 8; i++) {
        float4 v0, v1;
        v0.x = 1.f / (1.f + __expf(-acc[i][0]));
        v0.y = 1.f / (1.f + __expf(-acc[i][1]));
        v0.z = 1.f / (1.f + __expf(-acc[i][2]));
        v0.w = 1.f / (1.f + __expf(-acc[i][3]));
        v1.x = 1.f / (1.f + __expf(-acc[i][4]));
        v1.y = 1.f / (1.f + __expf(-acc[i][5]));
        v1.z = 1.f / (1.f + __expf(-acc[i][6]));
        v1.w = 1.f / (1.f + __expf(-acc[i][7]));
        *(float4*)(Cp + (size_t)i * NDIM)     = v0;
        *(float4*)(Cp + (size_t)i * NDIM + 4) = v1;
    }
}

extern "C" void kernel_launch(void* const* d_in, const int* in_sizes, int n_in,
                              void* d_out, int out_size) {
    const float* inputs = (const float*)d_in[0];   // [8,8,1024,256] fp32
    const float* Bw     = (const float*)d_in[1];   // [8,256,256]    fp32
    float* out          = (float*)d_out;           // [8,8,1024,1024] fp32

    dim3 g1(FDIM / 128, NDIM / 128, BDIM * RDIM);  // (2, 8, 64)
    bilinear_gemm1<<<g1, 256>>>(inputs, Bw);

    dim3 g2(NDIM / 128, NDIM / 128, BDIM * RDIM);  // (8, 8, 64)
    bilinear_gemm2<<<g2, 256>>>(inputs, out);
}

// round 5
// speedup vs baseline: 2.9678x; 2.9662x over previous
#include <cuda_runtime.h>
#include <cstdint>
#include <cstddef>

#define NDIM 1024
#define KDIM 256
#define BATCH 64   // B*R
#define RDIM 8

// Device-global scratch (no runtime allocation)
__device__ float g_e[(size_t)BATCH * NDIM * KDIM];    // e = G@Bs, rn-tf32 values
__device__ float g_in[(size_t)BATCH * NDIM * KDIM];   // inputs, rn-tf32
__device__ float g_inT[(size_t)BATCH * KDIM * NDIM];  // inputs transposed [br][f][n], rn-tf32
__device__ float g_bs[(size_t)RDIM * KDIM * KDIM];    // Bs, rn-tf32 (k-major already)

__device__ __forceinline__ float f2tf32(float x) {
    uint32_t o;
    asm("cvt.rna.tf32.f32 %0, %1;" : "=r"(o) : "f"(x));
    return __uint_as_float(o);
}
__device__ __forceinline__ uint32_t smem_u32(const void* p) {
    uint32_t a;
    asm("{ .reg .u64 t; cvta.to.shared.u64 t, %1; cvt.u32.u64 %0, t; }" : "=r"(a) : "l"(p));
    return a;
}
__device__ __forceinline__ void cp16(uint32_t dst, const float* src) {
    asm volatile("cp.async.cg.shared.global [%0], [%1], 16;" :: "r"(dst), "l"(src));
}

// ---------------------------------------------------------------- pre-passes
__global__ void cvt_kernel(const float* __restrict__ in, float* __restrict__ out, int n4) {
    int i = blockIdx.x * blockDim.x + threadIdx.x;
    if (i < n4) {
        float4 v = ((const float4*)in)[i];
        v.x = f2tf32(v.x); v.y = f2tf32(v.y); v.z = f2tf32(v.z); v.w = f2tf32(v.w);
        ((float4*)out)[i] = v;
    }
}
__global__ void cvt_transpose(const float* __restrict__ in, float* __restrict__ out) {
    __shared__ float t[32][33];
    const int br = blockIdx.z;
    const int n0 = blockIdx.x * 32, f0 = blockIdx.y * 32;
    const int tx = threadIdx.x, ty = threadIdx.y;       // 32 x 8
    const float* src = in + (size_t)br * NDIM * KDIM;
    float* dst = out + (size_t)br * KDIM * NDIM;
    for (int i = ty; i < 32; i += 8) t[i][tx] = src[(size_t)(n0 + i) * KDIM + f0 + tx];
    __syncthreads();
    for (int i = ty; i < 32; i += 8)
        dst[(size_t)(f0 + i) * NDIM + n0 + tx] = f2tf32(t[tx][i]);
}

// ---------------------------------------------------------------- tf32 mma.sync GEMM
// C[128 x 128 tile] = A[128 x 256] (row-major, k contiguous) @ B(k-major rows of n)
// 8 warps (2 m x 4 n), warp tile 64x32, m16n8k8 tf32 MMA, cp.async double buffer.
#define MMA_TF32(c, a, b)                                                       \
    asm volatile(                                                               \
        "mma.sync.aligned.m16n8k8.row.col.f32.tf32.tf32.f32 "                   \
        "{%0,%1,%2,%3}, {%4,%5,%6,%7}, {%8,%9}, {%0,%1,%2,%3};"                 \
        : "+f"((c)[0]), "+f"((c)[1]), "+f"((c)[2]), "+f"((c)[3])                \
        : "r"((a)[0]), "r"((a)[1]), "r"((a)[2]), "r"((a)[3]),                   \
          "r"((b)[0]), "r"((b)[1]))

template<int EPI>   // 0: store rn-tf32 (gemm1) ; 1: sigmoid (gemm2)
__global__ __launch_bounds__(256, 2)
void mma_gemm(const float* __restrict__ Ab, const float* __restrict__ Bb,
              float* __restrict__ Cb,
              int ldA, int ldB, int ldC, int bsel,
              size_t aStride, size_t bStride, size_t cStride) {
    constexpr int LDA_S = 36;    // A smem row pitch (floats): (4r+k)%32 distinct
    constexpr int LDB_S = 136;   // B smem row pitch (floats): (8k+c)%32 distinct
    constexpr uint32_t A_STAGE = 128u * LDA_S * 4u;   // 18432 B
    constexpr uint32_t B_STAGE = 32u * LDB_S * 4u;    // 17408 B
    constexpr uint32_t B_OFF   = 2u * A_STAGE;        // 36864
    constexpr int NCH = KDIM / 32;                    // 8 chunks

    extern __shared__ char smem[];
    const uint32_t sb = smem_u32(smem);
    float* Asm = (float*)smem;
    float* Bsm = (float*)(smem + B_OFF);

    const int tid  = threadIdx.x;
    const int warp = tid >> 5, lane = tid & 31;
    const int wm = warp >> 2, wn = warp & 3;          // 2 x 4
    const int tile_n = blockIdx.x, tile_m = blockIdx.y, br = blockIdx.z;

    const float* A = Ab + (size_t)br * aStride + (size_t)tile_m * 128 * ldA;
    const float* B = Bb + (size_t)(bsel ? (br & 7) : br) * bStride + (size_t)tile_n * 128;
    float* C = Cb + (size_t)br * cStride + (size_t)tile_m * 128 * ldC + (size_t)tile_n * 128;

    float acc[4][4][4];
    #pragma unroll
    for (int i = 0; i < 4; i++)
        #pragma unroll
        for (int j = 0; j < 4; j++)
            #pragma unroll
            for (int q = 0; q < 4; q++) acc[i][j][q] = 0.f;

    auto load_chunk = [&](int c, int s) {
        const int k0 = c * 32;
        // A: 128 rows x 32 floats (128 B/row) = 1024 x 16B ; 4 per thread
        const uint32_t ab = sb + (uint32_t)s * A_STAGE;
        #pragma unroll
        for (int j = 0; j < 4; j++) {
            const int idx = tid + j * 256;
            const int row = idx >> 3, c4 = idx & 7;
            cp16(ab + (uint32_t)(row * (LDA_S * 4) + c4 * 16),
                 A + (size_t)row * ldA + k0 + c4 * 4);
        }
        // B: 32 k-rows x 128 floats (512 B/row) = 1024 x 16B ; 4 per thread
        const uint32_t bb = sb + B_OFF + (uint32_t)s * B_STAGE;
        #pragma unroll
        for (int j = 0; j < 4; j++) {
            const int idx = tid + j * 256;
            const int row = idx >> 5, c4 = idx & 31;
            cp16(bb + (uint32_t)(row * (LDB_S * 4) + c4 * 16),
                 B + (size_t)(k0 + row) * ldB + c4 * 4);
        }
        asm volatile("cp.async.commit_group;" ::: "memory");
    };

    load_chunk(0, 0);

    for (int c = 0; c < NCH; c++) {
        const int s = c & 1;
        if (c + 1 < NCH) {
            load_chunk(c + 1, s ^ 1);
            asm volatile("cp.async.wait_group 1;" ::: "memory");
        } else {
            asm volatile("cp.async.wait_group 0;" ::: "memory");
        }
        __syncthreads();

        const float* Af = Asm + (size_t)s * (A_STAGE / 4);
        const float* Bf = Bsm + (size_t)s * (B_STAGE / 4);

        #pragma unroll
        for (int k8 = 0; k8 < 4; k8++) {
            const int kb = k8 * 8;
            uint32_t a[4][4], b[4][2];
            const int ar = wm * 64 + (lane >> 2);
            const int ak = kb + (lane & 3);
            #pragma unroll
            for (int mt = 0; mt < 4; mt++) {
                const int r = ar + mt * 16;
                a[mt][0] = __float_as_uint(Af[(size_t)r * LDA_S + ak]);
                a[mt][1] = __float_as_uint(Af[(size_t)(r + 8) * LDA_S + ak]);
                a[mt][2] = __float_as_uint(Af[(size_t)r * LDA_S + ak + 4]);
                a[mt][3] = __float_as_uint(Af[(size_t)(r + 8) * LDA_S + ak + 4]);
            }
            const int bk = kb + (lane & 3);
            const int bc = wn * 32 + (lane >> 2);
            #pragma unroll
            for (int nt = 0; nt < 4; nt++) {
                b[nt][0] = __float_as_uint(Bf[(size_t)bk * LDB_S + bc + nt * 8]);
                b[nt][1] = __float_as_uint(Bf[(size_t)(bk + 4) * LDB_S + bc + nt * 8]);
            }
            #pragma unroll
            for (int mt = 0; mt < 4; mt++)
                #pragma unroll
                for (int nt = 0; nt < 4; nt++)
                    MMA_TF32(acc[mt][nt], a[mt], b[nt]);
        }
        __syncthreads();
    }

    // Epilogue
    const int rbase = wm * 64 + (lane >> 2);
    const int cbase = wn * 32 + 2 * (lane & 3);
    #pragma unroll
    for (int mt = 0; mt < 4; mt++) {
        const int r = rbase + mt * 16;
        #pragma unroll
        for (int nt = 0; nt < 4; nt++) {
            const int cc = cbase + nt * 8;
            float2 v0, v1;
            if (EPI == 1) {
                v0.x = 1.f / (1.f + __expf(-acc[mt][nt][0]));
                v0.y = 1.f / (1.f + __expf(-acc[mt][nt][1]));
                v1.x = 1.f / (1.f + __expf(-acc[mt][nt][2]));
                v1.y = 1.f / (1.f + __expf(-acc[mt][nt][3]));
            } else {
                v0.x = f2tf32(acc[mt][nt][0]);
                v0.y = f2tf32(acc[mt][nt][1]);
                v1.x = f2tf32(acc[mt][nt][2]);
                v1.y = f2tf32(acc[mt][nt][3]);
            }
            *(float2*)(C + (size_t)r * ldC + cc) = v0;
            *(float2*)(C + (size_t)(r + 8) * ldC + cc) = v1;
        }
    }
}

// ---------------------------------------------------------------- launch
extern "C" void kernel_launch(void* const* d_in, const int* in_sizes, int n_in,
                              void* d_out, int out_size) {
    const float* inputs = (const float*)d_in[0];   // [8,8,1024,256]
    const float* Bw     = (const float*)d_in[1];   // [8,256,256]
    float* out          = (float*)d_out;           // [8,8,1024,1024]

    float *pe, *pin, *pinT, *pbs;
    cudaGetSymbolAddress((void**)&pe,   g_e);
    cudaGetSymbolAddress((void**)&pin,  g_in);
    cudaGetSymbolAddress((void**)&pinT, g_inT);
    cudaGetSymbolAddress((void**)&pbs,  g_bs);

    // Pre-passes: rn-tf32 copies
    const int n4i = (BATCH * NDIM * KDIM) / 4;
    cvt_kernel<<<(n4i + 255) / 256, 256>>>(inputs, pin, n4i);
    const int n4b = (RDIM * KDIM * KDIM) / 4;
    cvt_kernel<<<(n4b + 255) / 256, 256>>>(Bw, pbs, n4b);
    cvt_transpose<<<dim3(NDIM / 32, KDIM / 32, BATCH), dim3(32, 8)>>>(inputs, pinT);

    const size_t smemB = 2 * (128 * 36 * 4) + 2 * (32 * 136 * 4);  // 71680
    cudaFuncSetAttribute(mma_gemm<0>, cudaFuncAttributeMaxDynamicSharedMemorySize, (int)smemB);
    cudaFuncSetAttribute(mma_gemm<1>, cudaFuncAttributeMaxDynamicSharedMemorySize, (int)smemB);

    // GEMM1: e[1024,256] = in @ Bs   (B = g_bs[f][g], k-major rows)
    mma_gemm<0><<<dim3(KDIM / 128, NDIM / 128, BATCH), 256, smemB>>>(
        pin, pbs, pe,
        KDIM, KDIM, KDIM, /*bsel=*/1,
        (size_t)NDIM * KDIM, (size_t)KDIM * KDIM, (size_t)NDIM * KDIM);

    // GEMM2: scores[1024,1024] = e @ inT ; sigmoid
    mma_gemm<1><<<dim3(NDIM / 128, NDIM / 128, BATCH), 256, smemB>>>(
        pe, pinT, out,
        KDIM, NDIM, NDIM, /*bsel=*/0,
        (size_t)NDIM * KDIM, (size_t)KDIM * NDIM, (size_t)NDIM * NDIM);
}

// round 6
// speedup vs baseline: 3.9119x; 1.3181x over previous
#include <cuda_runtime.h>
#include <cstdint>
#include <cstddef>

#define NDIM 1024
#define KDIM 256
#define BATCH 64   // B*R
#define RDIM 8

// Device-global scratch (no runtime allocation)
__device__ float g_e[(size_t)BATCH * NDIM * KDIM];    // e = G@Bs, rn-tf32 values
__device__ float g_in[(size_t)BATCH * NDIM * KDIM];   // inputs, rn-tf32
__device__ float g_bsT[(size_t)RDIM * KDIM * KDIM];   // Bs transposed [r][g][f], rn-tf32

__device__ __forceinline__ float f2tf32(float x) {
    uint32_t o;
    asm("cvt.rna.tf32.f32 %0, %1;" : "=r"(o) : "f"(x));
    return __uint_as_float(o);
}
__device__ __forceinline__ uint32_t smem_u32(const void* p) {
    uint32_t a;
    asm("{ .reg .u64 t; cvta.to.shared.u64 t, %1; cvt.u32.u64 %0, t; }" : "=r"(a) : "l"(p));
    return a;
}
__device__ __forceinline__ void cp16(uint32_t dst, const float* src) {
    asm volatile("cp.async.cg.shared.global [%0], [%1], 16;" :: "r"(dst), "l"(src));
}

#define LDMX4(r0, r1, r2, r3, addr)                                             \
    asm volatile("ldmatrix.sync.aligned.m8n8.x4.shared.b16 {%0,%1,%2,%3}, [%4];"\
        : "=r"(r0), "=r"(r1), "=r"(r2), "=r"(r3) : "r"(addr))

#define MMA_TF32(c, a, b)                                                       \
    asm volatile(                                                               \
        "mma.sync.aligned.m16n8k8.row.col.f32.tf32.tf32.f32 "                   \
        "{%0,%1,%2,%3}, {%4,%5,%6,%7}, {%8,%9}, {%0,%1,%2,%3};"                 \
        : "+f"((c)[0]), "+f"((c)[1]), "+f"((c)[2]), "+f"((c)[3])                \
        : "r"((a)[0]), "r"((a)[1]), "r"((a)[2]), "r"((a)[3]),                   \
          "r"((b)[0]), "r"((b)[1]))

// ---------------------------------------------------------------- pre-passes
__global__ void cvt_kernel(const float* __restrict__ in, float* __restrict__ out, int n4) {
    int i = blockIdx.x * blockDim.x + threadIdx.x;
    if (i < n4) {
        float4 v = ((const float4*)in)[i];
        v.x = f2tf32(v.x); v.y = f2tf32(v.y); v.z = f2tf32(v.z); v.w = f2tf32(v.w);
        ((float4*)out)[i] = v;
    }
}
__global__ void transpose_bs(const float* __restrict__ Bs, float* __restrict__ BsT) {
    __shared__ float t[32][33];
    const int r = blockIdx.z;
    const int f0 = blockIdx.x * 32, g0 = blockIdx.y * 32;
    const int tx = threadIdx.x, ty = threadIdx.y;       // 32 x 8
    const float* src = Bs + (size_t)r * KDIM * KDIM;
    float* dst = BsT + (size_t)r * KDIM * KDIM;
    for (int i = ty; i < 32; i += 8) t[i][tx] = src[(size_t)(f0 + i) * KDIM + g0 + tx];
    __syncthreads();
    for (int i = ty; i < 32; i += 8)
        dst[(size_t)(g0 + i) * KDIM + f0 + tx] = f2tf32(t[tx][i]);
}

// ---------------------------------------------------------------- tf32 mma GEMM
// C[128x128 tile] = A[128 x K] (row-major) @ B[128 x K]^T (n-major rows).
// 8 warps (2m x 4n), warp tile 64x32, ldmatrix fragments, 3-stage cp.async.
// Smem tiles: 128 rows x 32 floats (128 B rows), XOR-16B swizzle.
template<int EPI>   // 0: store rn-tf32 (gemm1) ; 1: sigmoid (gemm2)
__global__ __launch_bounds__(256, 2)
void mma_gemm(const float* __restrict__ Ab, const float* __restrict__ Bb,
              float* __restrict__ Cb,
              int ldC, int bsel, size_t bStride, size_t cStride) {
    constexpr uint32_t STG = 128u * 128u;       // 16 KB per tile-stage
    constexpr uint32_t B_OFF = 3u * STG;        // B stages after 3 A stages
    constexpr int NCH = KDIM / 32;              // 8 k-chunks

    extern __shared__ char smem[];
    const uint32_t sb = smem_u32(smem);

    const int tid  = threadIdx.x;
    const int warp = tid >> 5, lane = tid & 31;
    const int wm = warp >> 2, wn = warp & 3;    // 2 x 4
    const int tile_n = blockIdx.x, tile_m = blockIdx.y, br = blockIdx.z;

    const float* A = Ab + (size_t)br * NDIM * KDIM + (size_t)tile_m * 128 * KDIM;
    const float* B = Bb + (size_t)(bsel ? (br & 7) : br) * bStride + (size_t)tile_n * 128 * KDIM;
    float* C = Cb + (size_t)br * cStride + (size_t)tile_m * 128 * ldC + (size_t)tile_n * 128;

    float acc[4][4][4];
    #pragma unroll
    for (int i = 0; i < 4; i++)
        #pragma unroll
        for (int j = 0; j < 4; j++)
            #pragma unroll
            for (int q = 0; q < 4; q++) acc[i][j][q] = 0.f;

    // cp.async mapping: 1024 16B-chunks per tile, 4 per thread
    auto load_chunk = [&](int c, int s) {
        const int k0 = c * 32;
        const uint32_t ab = sb + (uint32_t)s * STG;
        const uint32_t bb = sb + B_OFF + (uint32_t)s * STG;
        #pragma unroll
        for (int j = 0; j < 4; j++) {
            const int idx = tid + j * 256;
            const int row = idx >> 3, cc = idx & 7;
            const uint32_t off = (uint32_t)(row * 128 + ((cc ^ (row & 7)) << 4));
            cp16(ab + off, A + (size_t)row * KDIM + k0 + cc * 4);
            cp16(bb + off, B + (size_t)row * KDIM + k0 + cc * 4);
        }
        asm volatile("cp.async.commit_group;" ::: "memory");
    };

    load_chunk(0, 0);
    load_chunk(1, 1);

    // ldmatrix per-lane row/phase decomposition
    const int l7 = lane & 7;
    const int arow_in16 = l7 + ((lane >> 3) & 1) * 8;   // row within 16-block (a0/a1 split)
    const int pa = lane >> 4;                           // chunk half (a0a1 vs a2a3)
    const int bnt_half = (lane >> 4) & 1;               // nt offset within x4
    const int pb = (lane >> 3) & 1;                     // b0 vs b1 (k half)

    #pragma unroll 1
    for (int c = 0; c < NCH; c++) {
        const int s = c - (c / 3) * 3;                  // c % 3
        if (c + 2 < NCH) asm volatile("cp.async.wait_group 1;" ::: "memory");
        else             asm volatile("cp.async.wait_group 0;" ::: "memory");
        __syncthreads();

        const uint32_t Af = sb + (uint32_t)s * STG;
        const uint32_t Bf = sb + B_OFF + (uint32_t)s * STG;

        #pragma unroll
        for (int k8 = 0; k8 < 4; k8++) {
            uint32_t a[4][4], b[4][2];
            #pragma unroll
            for (int mt = 0; mt < 4; mt++) {
                const int r = wm * 64 + mt * 16 + arow_in16;
                const uint32_t addr = Af + (uint32_t)(r * 128 + (((k8 * 2 + pa) ^ (r & 7)) << 4));
                LDMX4(a[mt][0], a[mt][1], a[mt][2], a[mt][3], addr);
            }
            #pragma unroll
            for (int q = 0; q < 2; q++) {
                const int nt = q * 2 + bnt_half;
                const int r = wn * 32 + nt * 8 + l7;
                const uint32_t addr = Bf + (uint32_t)(r * 128 + (((k8 * 2 + pb) ^ (r & 7)) << 4));
                LDMX4(b[q * 2][0], b[q * 2][1], b[q * 2 + 1][0], b[q * 2 + 1][1], addr);
            }
            #pragma unroll
            for (int mt = 0; mt < 4; mt++)
                #pragma unroll
                for (int nt = 0; nt < 4; nt++)
                    MMA_TF32(acc[mt][nt], a[mt], b[nt]);
        }

        if (c + 2 < NCH) load_chunk(c + 2, (c + 2) - ((c + 2) / 3) * 3);
    }

    // Epilogue
    const int rbase = wm * 64 + (lane >> 2);
    const int cbase = wn * 32 + 2 * (lane & 3);
    #pragma unroll
    for (int mt = 0; mt < 4; mt++) {
        const int r = rbase + mt * 16;
        #pragma unroll
        for (int nt = 0; nt < 4; nt++) {
            const int cc = cbase + nt * 8;
            float2 v0, v1;
            if (EPI == 1) {
                v0.x = 1.f / (1.f + __expf(-acc[mt][nt][0]));
                v0.y = 1.f / (1.f + __expf(-acc[mt][nt][1]));
                v1.x = 1.f / (1.f + __expf(-acc[mt][nt][2]));
                v1.y = 1.f / (1.f + __expf(-acc[mt][nt][3]));
            } else {
                v0.x = f2tf32(acc[mt][nt][0]);
                v0.y = f2tf32(acc[mt][nt][1]);
                v1.x = f2tf32(acc[mt][nt][2]);
                v1.y = f2tf32(acc[mt][nt][3]);
            }
            *(float2*)(C + (size_t)r * ldC + cc) = v0;
            *(float2*)(C + (size_t)(r + 8) * ldC + cc) = v1;
        }
    }
}

// ---------------------------------------------------------------- launch
extern "C" void kernel_launch(void* const* d_in, const int* in_sizes, int n_in,
                              void* d_out, int out_size) {
    const float* inputs = (const float*)d_in[0];   // [8,8,1024,256]
    const float* Bw     = (const float*)d_in[1];   // [8,256,256]
    float* out          = (float*)d_out;           // [8,8,1024,1024]

    float *pe, *pin, *pbsT;
    cudaGetSymbolAddress((void**)&pe,   g_e);
    cudaGetSymbolAddress((void**)&pin,  g_in);
    cudaGetSymbolAddress((void**)&pbsT, g_bsT);

    // rn-tf32 pre-passes
    const int n4i = (BATCH * NDIM * KDIM) / 4;
    cvt_kernel<<<(n4i + 255) / 256, 256>>>(inputs, pin, n4i);
    transpose_bs<<<dim3(8, 8, 8), dim3(32, 8)>>>(Bw, pbsT);

    const size_t smemB = 6 * 128 * 128;   // 3 stages x (A 16K + B 16K) = 96 KB
    cudaFuncSetAttribute(mma_gemm<0>, cudaFuncAttributeMaxDynamicSharedMemorySize, (int)smemB);
    cudaFuncSetAttribute(mma_gemm<1>, cudaFuncAttributeMaxDynamicSharedMemorySize, (int)smemB);

    // GEMM1: e[1024,256] = in @ bsT^T   (B n-major: bsT[g][f])
    mma_gemm<0><<<dim3(KDIM / 128, NDIM / 128, BATCH), 256, smemB>>>(
        pin, pbsT, pe,
        KDIM, /*bsel=*/1, (size_t)KDIM * KDIM, (size_t)NDIM * KDIM);

    // GEMM2: scores = e @ in^T ; sigmoid  (B n-major: in[n][f])
    mma_gemm<1><<<dim3(NDIM / 128, NDIM / 128, BATCH), 256, smemB>>>(
        pe, pin, out,
        NDIM, /*bsel=*/0, (size_t)NDIM * KDIM, (size_t)NDIM * NDIM);
}

// round 7
// speedup vs baseline: 5.4763x; 1.3999x over previous
#include <cuda_runtime.h>
#include <cuda_fp16.h>
#include <cstdint>
#include <cstddef>

#define NDIM 1024
#define KDIM 256
#define BATCH 64   // B*R
#define RDIM 8

// Device-global scratch (no runtime allocation)
__device__ __half g_e[(size_t)BATCH * NDIM * KDIM];    // e = G@Bs, fp16
__device__ __half g_in[(size_t)BATCH * NDIM * KDIM];   // inputs, fp16
__device__ __half g_bsT[(size_t)RDIM * KDIM * KDIM];   // Bs transposed [r][g][f], fp16

__device__ __forceinline__ uint32_t smem_u32(const void* p) {
    uint32_t a;
    asm("{ .reg .u64 t; cvta.to.shared.u64 t, %1; cvt.u32.u64 %0, t; }" : "=r"(a) : "l"(p));
    return a;
}
__device__ __forceinline__ void cp16(uint32_t dst, const void* src) {
    asm volatile("cp.async.cg.shared.global [%0], [%1], 16;" :: "r"(dst), "l"(src));
}

#define LDMX4(r0, r1, r2, r3, addr)                                             \
    asm volatile("ldmatrix.sync.aligned.m8n8.x4.shared.b16 {%0,%1,%2,%3}, [%4];"\
        : "=r"(r0), "=r"(r1), "=r"(r2), "=r"(r3) : "r"(addr))

// m16n8k16 fp16 MMA, fp32 accum
#define MMA_F16(c, a, b)                                                        \
    asm volatile(                                                               \
        "mma.sync.aligned.m16n8k16.row.col.f32.f16.f16.f32 "                    \
        "{%0,%1,%2,%3}, {%4,%5,%6,%7}, {%8,%9}, {%0,%1,%2,%3};"                 \
        : "+f"((c)[0]), "+f"((c)[1]), "+f"((c)[2]), "+f"((c)[3])                \
        : "r"((a)[0]), "r"((a)[1]), "r"((a)[2]), "r"((a)[3]),                   \
          "r"((b)[0]), "r"((b)[1]))

// ---------------------------------------------------------------- pre-passes
__global__ void cvt_f2h(const float* __restrict__ in, __half* __restrict__ out, int n4) {
    int i = blockIdx.x * blockDim.x + threadIdx.x;
    if (i < n4) {
        float4 v = ((const float4*)in)[i];
        __half2 h0 = __floats2half2_rn(v.x, v.y);
        __half2 h1 = __floats2half2_rn(v.z, v.w);
        ((__half2*)out)[i * 2]     = h0;
        ((__half2*)out)[i * 2 + 1] = h1;
    }
}
__global__ void transpose_bs(const float* __restrict__ Bs, __half* __restrict__ BsT) {
    __shared__ float t[32][33];
    const int r = blockIdx.z;
    const int f0 = blockIdx.x * 32, g0 = blockIdx.y * 32;
    const int tx = threadIdx.x, ty = threadIdx.y;       // 32 x 8
    const float* src = Bs + (size_t)r * KDIM * KDIM;
    __half* dst = BsT + (size_t)r * KDIM * KDIM;
    for (int i = ty; i < 32; i += 8) t[i][tx] = src[(size_t)(f0 + i) * KDIM + g0 + tx];
    __syncthreads();
    for (int i = ty; i < 32; i += 8)
        dst[(size_t)(g0 + i) * KDIM + f0 + tx] = __float2half_rn(t[tx][i]);
}

// ---------------------------------------------------------------- fp16 mma GEMM
// C[128x128 tile] = A[128 x 256] (row-major fp16) @ B[128 x 256]^T (n-major fp16).
// 8 warps (2m x 4n), warp tile 64x32, m16n8k16, ldmatrix, 3-stage cp.async.
// Smem stage: 128 rows x 64 halves (128 B rows), XOR-16B swizzle; k-chunk = 64.
template<int EPI>   // 0: store fp16 (gemm1 -> g_e) ; 1: sigmoid fp32 (gemm2 -> out)
__global__ __launch_bounds__(256, 2)
void mma_gemm(const __half* __restrict__ Ab, const __half* __restrict__ Bb,
              void* __restrict__ Cb,
              int ldC, int bsel, size_t bStride, size_t cStride) {
    constexpr uint32_t STG = 128u * 128u;       // 16 KB per tile-stage
    constexpr uint32_t B_OFF = 3u * STG;
    constexpr int NCH = KDIM / 64;              // 4 k-chunks

    extern __shared__ char smem[];
    const uint32_t sb = smem_u32(smem);

    const int tid  = threadIdx.x;
    const int warp = tid >> 5, lane = tid & 31;
    const int wm = warp >> 2, wn = warp & 3;    // 2 x 4
    const int tile_n = blockIdx.x, tile_m = blockIdx.y, br = blockIdx.z;

    const __half* A = Ab + (size_t)br * NDIM * KDIM + (size_t)tile_m * 128 * KDIM;
    const __half* B = Bb + (size_t)(bsel ? (br & 7) : br) * bStride + (size_t)tile_n * 128 * KDIM;

    float acc[4][4][4];
    #pragma unroll
    for (int i = 0; i < 4; i++)
        #pragma unroll
        for (int j = 0; j < 4; j++)
            #pragma unroll
            for (int q = 0; q < 4; q++) acc[i][j][q] = 0.f;

    // cp.async: 1024 16B-chunks per tile (128 rows x 8), 4 per thread
    auto load_chunk = [&](int c, int s) {
        const int k0 = c * 64;                  // halves
        const uint32_t ab = sb + (uint32_t)s * STG;
        const uint32_t bb = sb + B_OFF + (uint32_t)s * STG;
        #pragma unroll
        for (int j = 0; j < 4; j++) {
            const int idx = tid + j * 256;
            const int row = idx >> 3, cc = idx & 7;
            const uint32_t off = (uint32_t)(row * 128 + ((cc ^ (row & 7)) << 4));
            cp16(ab + off, A + (size_t)row * KDIM + k0 + cc * 8);
            cp16(bb + off, B + (size_t)row * KDIM + k0 + cc * 8);
        }
        asm volatile("cp.async.commit_group;" ::: "memory");
    };

    load_chunk(0, 0);
    load_chunk(1, 1);

    // ldmatrix lane decomposition (16B-chunk granular; identical to tf32 layout)
    const int l7 = lane & 7;
    const int arow_in16 = l7 + ((lane >> 3) & 1) * 8;
    const int pa = lane >> 4;                   // A: k-half of 16x16 fragment
    const int bnt_half = (lane >> 4) & 1;       // B: nt within x4
    const int pb = (lane >> 3) & 1;             // B: k-half

    #pragma unroll 1
    for (int c = 0; c < NCH; c++) {
        const int s = c - (c / 3) * 3;          // c % 3
        if (c + 2 < NCH) asm volatile("cp.async.wait_group 1;" ::: "memory");
        else             asm volatile("cp.async.wait_group 0;" ::: "memory");
        __syncthreads();

        const uint32_t Af = sb + (uint32_t)s * STG;
        const uint32_t Bf = sb + B_OFF + (uint32_t)s * STG;

        #pragma unroll
        for (int k16 = 0; k16 < 4; k16++) {     // 16 halves per step, 4 steps = 64
            uint32_t a[4][4], b[4][2];
            #pragma unroll
            for (int mt = 0; mt < 4; mt++) {
                const int r = wm * 64 + mt * 16 + arow_in16;
                const uint32_t addr = Af + (uint32_t)(r * 128 + (((k16 * 2 + pa) ^ (r & 7)) << 4));
                LDMX4(a[mt][0], a[mt][1], a[mt][2], a[mt][3], addr);
            }
            #pragma unroll
            for (int q = 0; q < 2; q++) {
                const int r = wn * 32 + (q * 2 + bnt_half) * 8 + l7;
                const uint32_t addr = Bf + (uint32_t)(r * 128 + (((k16 * 2 + pb) ^ (r & 7)) << 4));
                LDMX4(b[q * 2][0], b[q * 2][1], b[q * 2 + 1][0], b[q * 2 + 1][1], addr);
            }
            #pragma unroll
            for (int mt = 0; mt < 4; mt++)
                #pragma unroll
                for (int nt = 0; nt < 4; nt++)
                    MMA_F16(acc[mt][nt], a[mt], b[nt]);
        }

        if (c + 2 < NCH) load_chunk(c + 2, (c + 2) - ((c + 2) / 3) * 3);
    }

    // Epilogue: thread holds (r,c),(r,c+1) and (r+8,c),(r+8,c+1) per (mt,nt)
    const int rbase = wm * 64 + (lane >> 2);
    const int cbase = wn * 32 + 2 * (lane & 3);
    if (EPI == 0) {
        __half* C = (__half*)Cb + (size_t)br * cStride +
                    (size_t)(tile_m * 128) * ldC + tile_n * 128;
        #pragma unroll
        for (int mt = 0; mt < 4; mt++) {
            const int r = rbase + mt * 16;
            #pragma unroll
            for (int nt = 0; nt < 4; nt++) {
                const int cc = cbase + nt * 8;
                *(__half2*)(C + (size_t)r * ldC + cc) =
                    __floats2half2_rn(acc[mt][nt][0], acc[mt][nt][1]);
                *(__half2*)(C + (size_t)(r + 8) * ldC + cc) =
                    __floats2half2_rn(acc[mt][nt][2], acc[mt][nt][3]);
            }
        }
    } else {
        float* C = (float*)Cb + (size_t)br * cStride +
                   (size_t)(tile_m * 128) * ldC + tile_n * 128;
        #pragma unroll
        for (int mt = 0; mt < 4; mt++) {
            const int r = rbase + mt * 16;
            #pragma unroll
            for (int nt = 0; nt < 4; nt++) {
                const int cc = cbase + nt * 8;
                float2 v0, v1;
                v0.x = 1.f / (1.f + __expf(-acc[mt][nt][0]));
                v0.y = 1.f / (1.f + __expf(-acc[mt][nt][1]));
                v1.x = 1.f / (1.f + __expf(-acc[mt][nt][2]));
                v1.y = 1.f / (1.f + __expf(-acc[mt][nt][3]));
                *(float2*)(C + (size_t)r * ldC + cc) = v0;
                *(float2*)(C + (size_t)(r + 8) * ldC + cc) = v1;
            }
        }
    }
}

// ---------------------------------------------------------------- launch
extern "C" void kernel_launch(void* const* d_in, const int* in_sizes, int n_in,
                              void* d_out, int out_size) {
    const float* inputs = (const float*)d_in[0];   // [8,8,1024,256]
    const float* Bw     = (const float*)d_in[1];   // [8,256,256]
    float* out          = (float*)d_out;           // [8,8,1024,1024]

    __half *pe, *pin, *pbsT;
    cudaGetSymbolAddress((void**)&pe,   g_e);
    cudaGetSymbolAddress((void**)&pin,  g_in);
    cudaGetSymbolAddress((void**)&pbsT, g_bsT);

    // fp16 pre-passes
    const int n4i = (BATCH * NDIM * KDIM) / 4;
    cvt_f2h<<<(n4i + 255) / 256, 256>>>(inputs, pin, n4i);
    transpose_bs<<<dim3(8, 8, 8), dim3(32, 8)>>>(Bw, pbsT);

    const size_t smemB = 6 * 128 * 128;   // 3 stages x (A 16K + B 16K) = 96 KB
    cudaFuncSetAttribute(mma_gemm<0>, cudaFuncAttributeMaxDynamicSharedMemorySize, (int)smemB);
    cudaFuncSetAttribute(mma_gemm<1>, cudaFuncAttributeMaxDynamicSharedMemorySize, (int)smemB);

    // GEMM1: e[1024,256] = in @ bsT^T  (fp16 out)
    mma_gemm<0><<<dim3(KDIM / 128, NDIM / 128, BATCH), 256, smemB>>>(
        pin, pbsT, pe,
        KDIM, /*bsel=*/1, (size_t)KDIM * KDIM, (size_t)NDIM * KDIM);

    // GEMM2: scores = e @ in^T ; sigmoid (fp32 out)
    mma_gemm<1><<<dim3(NDIM / 128, NDIM / 128, BATCH), 256, smemB>>>(
        pe, pin, out,
        NDIM, /*bsel=*/0, (size_t)NDIM * KDIM, (size_t)NDIM * NDIM);
}